// round 3
// baseline (speedup 1.0000x reference)
#include <cuda_runtime.h>
#include <math.h>

#define B_      2
#define SEQ     1024
#define DIM_    1024
#define HEADS_  16
#define DH_     64
#define MLP_    4096
#define ROWS    (B_*SEQ)          // 2048
#define SCALE_  0.125f            // 64^-0.5
#define DEPTH_  2

// ---------------- scratch (device globals: allocation-guard-safe) -------------
__device__ float g_h   [ROWS*DIM_];        // 8 MB
__device__ float g_qkv [ROWS*3*DIM_];      // 24 MB
__device__ float g_q2  [ROWS*DIM_];
__device__ float g_k2  [ROWS*DIM_];
__device__ float g_v2  [ROWS*DIM_];
__device__ float g_o   [ROWS*DIM_];
__device__ float g_mlp [ROWS*MLP_];        // 32 MB
__device__ float g_s   [B_*HEADS_*SEQ*SEQ];// 128 MB scores

// ---------------- layernorm: one block per row ------------------------------
__global__ __launch_bounds__(256) void layernorm_k(
    const float* __restrict__ x, const float* __restrict__ g,
    const float* __restrict__ b, float* __restrict__ out)
{
    __shared__ float red[18];
    const int row = blockIdx.x;
    const int t   = threadIdx.x;
    const float4 v = ((const float4*)(x + (size_t)row*DIM_))[t];
    float s  = v.x + v.y + v.z + v.w;
    float sq = v.x*v.x + v.y*v.y + v.z*v.z + v.w*v.w;
    #pragma unroll
    for (int o = 16; o > 0; o >>= 1) {
        s  += __shfl_down_sync(0xffffffffu, s,  o);
        sq += __shfl_down_sync(0xffffffffu, sq, o);
    }
    if ((t & 31) == 0) { red[t >> 5] = s; red[8 + (t >> 5)] = sq; }
    __syncthreads();
    if (t < 32) {
        float a = (t < 8) ? red[t]     : 0.f;
        float c = (t < 8) ? red[8 + t] : 0.f;
        #pragma unroll
        for (int o = 4; o > 0; o >>= 1) {
            a += __shfl_down_sync(0xffffffffu, a, o);
            c += __shfl_down_sync(0xffffffffu, c, o);
        }
        if (t == 0) { red[16] = a; red[17] = c; }
    }
    __syncthreads();
    const float mu   = red[16] * (1.f / DIM_);
    const float var  = red[17] * (1.f / DIM_) - mu * mu;
    const float rstd = rsqrtf(var + 1e-5f);
    const float4 gv = ((const float4*)g)[t];
    const float4 bv = ((const float4*)b)[t];
    float4 o4;
    o4.x = (v.x - mu) * rstd * gv.x + bv.x;
    o4.y = (v.y - mu) * rstd * gv.y + bv.y;
    o4.z = (v.z - mu) * rstd * gv.z + bv.z;
    o4.w = (v.w - mu) * rstd * gv.w + bv.w;
    ((float4*)(out + (size_t)row*DIM_))[t] = o4;
}

// ---------------- SGEMM 128x128x8, 256 thr, 8x8 micro-tile -------------------
// C[M,N] = act(A[M,K] @ B[K,N] + bias) + res.   All dims % (128,128,8) == 0.
// act: 0 = none, 1 = exact GELU (x * Phi(x)).
__global__ __launch_bounds__(256) void sgemm_k(
    const float* __restrict__ A, const float* __restrict__ B,
    const float* __restrict__ bias, const float* __restrict__ res,
    float* __restrict__ C, int M, int N, int K, int act)
{
    __shared__ float As[8][128];
    __shared__ float Bs[8][128];
    const int tid = threadIdx.x;
    const int bm  = blockIdx.y, bn = blockIdx.x;
    const int tx  = tid & 15, ty = tid >> 4;

    const int a_row = tid >> 1;          // 0..127
    const int a_col = (tid & 1) * 4;     // 0 or 4
    const int b_row = tid >> 5;          // 0..7
    const int b_col = (tid & 31) * 4;    // 0..124
    const float* Ap = A + (size_t)(bm*128 + a_row) * K + a_col;
    const float* Bp = B + (size_t)b_row * N + bn*128 + b_col;

    float acc[8][8];
    #pragma unroll
    for (int i = 0; i < 8; i++)
        #pragma unroll
        for (int j = 0; j < 8; j++) acc[i][j] = 0.f;

    for (int kk = 0; kk < K; kk += 8) {
        const float4 av = *(const float4*)(Ap + kk);
        As[a_col + 0][a_row] = av.x;
        As[a_col + 1][a_row] = av.y;
        As[a_col + 2][a_row] = av.z;
        As[a_col + 3][a_row] = av.w;
        *(float4*)&Bs[b_row][b_col] = *(const float4*)(Bp + (size_t)kk * N);
        __syncthreads();
        #pragma unroll
        for (int k = 0; k < 8; k++) {
            float ar[8], br[8];
            const float4 a0 = *(const float4*)&As[k][ty*8];
            const float4 a1 = *(const float4*)&As[k][ty*8 + 4];
            ar[0]=a0.x; ar[1]=a0.y; ar[2]=a0.z; ar[3]=a0.w;
            ar[4]=a1.x; ar[5]=a1.y; ar[6]=a1.z; ar[7]=a1.w;
            const float4 b0 = *(const float4*)&Bs[k][tx*8];
            const float4 b1 = *(const float4*)&Bs[k][tx*8 + 4];
            br[0]=b0.x; br[1]=b0.y; br[2]=b0.z; br[3]=b0.w;
            br[4]=b1.x; br[5]=b1.y; br[6]=b1.z; br[7]=b1.w;
            #pragma unroll
            for (int i = 0; i < 8; i++)
                #pragma unroll
                for (int j = 0; j < 8; j++)
                    acc[i][j] = fmaf(ar[i], br[j], acc[i][j]);
        }
        __syncthreads();
    }

    float bj[8];
    #pragma unroll
    for (int j = 0; j < 8; j++)
        bj[j] = bias ? bias[bn*128 + tx*8 + j] : 0.f;

    #pragma unroll
    for (int i = 0; i < 8; i++) {
        const size_t row = (size_t)(bm*128 + ty*8 + i);
        #pragma unroll
        for (int j = 0; j < 8; j++) {
            const size_t idx = row * N + bn*128 + tx*8 + j;
            float v = acc[i][j] + bj[j];
            if (act == 1) v = v * normcdff(v);     // exact GELU
            if (res) v += res[idx];
            C[idx] = v;
        }
    }
}

// ---------------- attention: S = scale * Q K^T (per batch-head) --------------
// Q rows stride ldq (head h at column offset h*DH_ already folded into base ptr math)
__global__ __launch_bounds__(256) void attn_qk_k(
    const float* __restrict__ Q, int ldq,
    const float* __restrict__ Kp, int ldk,
    float* __restrict__ S)
{
    const int bh = blockIdx.z, b = bh >> 4, h = bh & 15;
    const int qt = blockIdx.y * 64, kt = blockIdx.x * 64;
    const float* qb = Q  + (size_t)(b*SEQ + qt) * ldq + h*DH_;
    const float* kb = Kp + (size_t)(b*SEQ + kt) * ldk + h*DH_;
    float* sb = g_s + (size_t)bh * SEQ * SEQ;   // ignore S param; use global directly
    (void)S;

    __shared__ float Qs[64][65];   // [d][n]
    __shared__ float Ks[64][65];   // [d][m]
    const int tid = threadIdx.x;
    for (int i = tid; i < 64*16; i += 256) {
        const int r = i >> 4, c4 = (i & 15) * 4;
        const float4 v = *(const float4*)(qb + (size_t)r*ldq + c4);
        Qs[c4+0][r]=v.x; Qs[c4+1][r]=v.y; Qs[c4+2][r]=v.z; Qs[c4+3][r]=v.w;
        const float4 w = *(const float4*)(kb + (size_t)r*ldk + c4);
        Ks[c4+0][r]=w.x; Ks[c4+1][r]=w.y; Ks[c4+2][r]=w.z; Ks[c4+3][r]=w.w;
    }
    __syncthreads();

    const int tx = tid & 15, ty = tid >> 4;
    float acc[4][4];
    #pragma unroll
    for (int i = 0; i < 4; i++)
        #pragma unroll
        for (int j = 0; j < 4; j++) acc[i][j] = 0.f;

    #pragma unroll 4
    for (int k = 0; k < 64; k++) {
        float ar[4], br[4];
        #pragma unroll
        for (int i = 0; i < 4; i++) ar[i] = Qs[k][ty*4 + i];
        #pragma unroll
        for (int j = 0; j < 4; j++) br[j] = Ks[k][tx*4 + j];
        #pragma unroll
        for (int i = 0; i < 4; i++)
            #pragma unroll
            for (int j = 0; j < 4; j++)
                acc[i][j] = fmaf(ar[i], br[j], acc[i][j]);
    }
    #pragma unroll
    for (int i = 0; i < 4; i++)
        #pragma unroll
        for (int j = 0; j < 4; j++)
            sb[(size_t)(qt + ty*4 + i) * SEQ + kt + tx*4 + j] = acc[i][j] * SCALE_;
}

// ---------------- row softmax over S (SEQ cols) -------------------------------
__global__ __launch_bounds__(256) void softmax_k()
{
    __shared__ float red[16];
    float* p = g_s + (size_t)blockIdx.x * SEQ;
    const int t = threadIdx.x;
    float4 v = ((float4*)p)[t];
    float m = fmaxf(fmaxf(v.x, v.y), fmaxf(v.z, v.w));
    #pragma unroll
    for (int o = 16; o > 0; o >>= 1) m = fmaxf(m, __shfl_xor_sync(0xffffffffu, m, o));
    if ((t & 31) == 0) red[t >> 5] = m;
    __syncthreads();
    m = red[0];
    #pragma unroll
    for (int i = 1; i < 8; i++) m = fmaxf(m, red[i]);

    v.x = __expf(v.x - m); v.y = __expf(v.y - m);
    v.z = __expf(v.z - m); v.w = __expf(v.w - m);
    float s = v.x + v.y + v.z + v.w;
    #pragma unroll
    for (int o = 16; o > 0; o >>= 1) s += __shfl_xor_sync(0xffffffffu, s, o);
    if ((t & 31) == 0) red[8 + (t >> 5)] = s;
    __syncthreads();
    s = red[8];
    #pragma unroll
    for (int i = 1; i < 8; i++) s += red[8 + i];
    const float inv = 1.f / s;
    v.x *= inv; v.y *= inv; v.z *= inv; v.w *= inv;
    ((float4*)p)[t] = v;
}

// ---------------- O = P @ V, writes merged-head layout ------------------------
__global__ __launch_bounds__(256) void attn_av_k(
    const float* __restrict__ V, int ldv, float* __restrict__ O)
{
    const int bh = blockIdx.y, b = bh >> 4, h = bh & 15;
    const int nt = blockIdx.x * 64;
    const float* sb = g_s + (size_t)bh * SEQ * SEQ + (size_t)nt * SEQ;
    const float* vb = V + (size_t)(b*SEQ) * ldv + h*DH_;
    float* ob = O + (size_t)(b*SEQ + nt) * DIM_ + h*DH_;

    __shared__ float Ps[64][65];   // [m][n]
    __shared__ float Vs[64][65];   // [m][d]
    const int tid = threadIdx.x;
    const int tx = tid & 15, ty = tid >> 4;
    float acc[4][4];
    #pragma unroll
    for (int i = 0; i < 4; i++)
        #pragma unroll
        for (int j = 0; j < 4; j++) acc[i][j] = 0.f;

    for (int mt = 0; mt < SEQ; mt += 64) {
        for (int i = tid; i < 64*16; i += 256) {
            const int r = i >> 4, c4 = (i & 15) * 4;
            const float4 v = *(const float4*)(sb + (size_t)r*SEQ + mt + c4);
            Ps[c4+0][r]=v.x; Ps[c4+1][r]=v.y; Ps[c4+2][r]=v.z; Ps[c4+3][r]=v.w;
            const float4 w = *(const float4*)(vb + (size_t)(mt + r)*ldv + c4);
            Vs[r][c4+0]=w.x; Vs[r][c4+1]=w.y; Vs[r][c4+2]=w.z; Vs[r][c4+3]=w.w;
        }
        __syncthreads();
        #pragma unroll 4
        for (int m = 0; m < 64; m++) {
            float pr[4], vr[4];
            #pragma unroll
            for (int i = 0; i < 4; i++) pr[i] = Ps[m][ty*4 + i];
            #pragma unroll
            for (int j = 0; j < 4; j++) vr[j] = Vs[m][tx*4 + j];
            #pragma unroll
            for (int i = 0; i < 4; i++)
                #pragma unroll
                for (int j = 0; j < 4; j++)
                    acc[i][j] = fmaf(pr[i], vr[j], acc[i][j]);
        }
        __syncthreads();
    }
    #pragma unroll
    for (int i = 0; i < 4; i++)
        #pragma unroll
        for (int j = 0; j < 4; j++)
            ob[(size_t)(ty*4 + i) * DIM_ + tx*4 + j] = acc[i][j];
}

// ---------------- host launch --------------------------------------------------
extern "C" void kernel_launch(void* const* d_in, const int* in_sizes, int n_in,
                              void* d_out, int out_size)
{
    (void)in_sizes; (void)n_in; (void)out_size;
    const float* x_in  = (const float*)d_in[0];
    const float* ctx   = (const float*)d_in[1];
    const float* ln1_g = (const float*)d_in[2];
    const float* ln1_b = (const float*)d_in[3];
    const float* w_qkv = (const float*)d_in[4];
    const float* w_o1  = (const float*)d_in[5];
    const float* b_o1  = (const float*)d_in[6];
    const float* ln2_g = (const float*)d_in[7];
    const float* ln2_b = (const float*)d_in[8];
    const float* w_q   = (const float*)d_in[9];
    const float* w_k   = (const float*)d_in[10];
    const float* w_v   = (const float*)d_in[11];
    const float* w_o2  = (const float*)d_in[12];
    const float* b_o2  = (const float*)d_in[13];
    const float* ln3_g = (const float*)d_in[14];
    const float* ln3_b = (const float*)d_in[15];
    const float* w_ff1 = (const float*)d_in[16];
    const float* b_ff1 = (const float*)d_in[17];
    const float* w_ff2 = (const float*)d_in[18];
    const float* b_ff2 = (const float*)d_in[19];

    float* x = (float*)d_out;           // running residual stream lives in d_out

    float *h, *qkv, *q2, *k2, *v2, *o, *mlp, *s;
    cudaGetSymbolAddress((void**)&h,   g_h);
    cudaGetSymbolAddress((void**)&qkv, g_qkv);
    cudaGetSymbolAddress((void**)&q2,  g_q2);
    cudaGetSymbolAddress((void**)&k2,  g_k2);
    cudaGetSymbolAddress((void**)&v2,  g_v2);
    cudaGetSymbolAddress((void**)&o,   g_o);
    cudaGetSymbolAddress((void**)&mlp, g_mlp);
    cudaGetSymbolAddress((void**)&s,   g_s);

    cudaMemcpyAsync(x, x_in, (size_t)ROWS * DIM_ * sizeof(float),
                    cudaMemcpyDeviceToDevice, 0);

    const dim3 gProj(DIM_/128,  ROWS/128);     // (8,16)  N=1024
    const dim3 gQKV(3*DIM_/128, ROWS/128);     // (24,16) N=3072
    const dim3 gFF1(MLP_/128,   ROWS/128);     // (32,16) N=4096
    const dim3 gQK(16, 16, B_*HEADS_);         // 64x64 score tiles
    const dim3 gAV(16, B_*HEADS_);

    for (int l = 0; l < DEPTH_; l++) {
        const float* wqkv_l = w_qkv + (size_t)l * DIM_ * 3*DIM_;
        const float* wo1_l  = w_o1  + (size_t)l * DIM_ * DIM_;
        const float* wq_l   = w_q   + (size_t)l * DIM_ * DIM_;
        const float* wk_l   = w_k   + (size_t)l * DIM_ * DIM_;
        const float* wv_l   = w_v   + (size_t)l * DIM_ * DIM_;
        const float* wo2_l  = w_o2  + (size_t)l * DIM_ * DIM_;
        const float* wff1_l = w_ff1 + (size_t)l * DIM_ * MLP_;
        const float* wff2_l = w_ff2 + (size_t)l * MLP_ * DIM_;

        // --- self attention ---
        layernorm_k<<<ROWS, 256>>>(x, ln1_g + l*DIM_, ln1_b + l*DIM_, h);
        sgemm_k<<<gQKV, 256>>>(h, wqkv_l, nullptr, nullptr, qkv,
                               ROWS, 3*DIM_, DIM_, 0);
        attn_qk_k<<<gQK, 256>>>(qkv, 3*DIM_, qkv + DIM_, 3*DIM_, s);
        softmax_k<<<B_*HEADS_*SEQ, 256>>>();
        attn_av_k<<<gAV, 256>>>(qkv + 2*DIM_, 3*DIM_, o);
        sgemm_k<<<gProj, 256>>>(o, wo1_l, b_o1 + l*DIM_, x, x,
                                ROWS, DIM_, DIM_, 0);

        // --- cross attention ---
        layernorm_k<<<ROWS, 256>>>(x, ln2_g + l*DIM_, ln2_b + l*DIM_, h);
        sgemm_k<<<gProj, 256>>>(h,   wq_l, nullptr, nullptr, q2, ROWS, DIM_, DIM_, 0);
        sgemm_k<<<gProj, 256>>>(ctx, wk_l, nullptr, nullptr, k2, ROWS, DIM_, DIM_, 0);
        sgemm_k<<<gProj, 256>>>(ctx, wv_l, nullptr, nullptr, v2, ROWS, DIM_, DIM_, 0);
        attn_qk_k<<<gQK, 256>>>(q2, DIM_, k2, DIM_, s);
        softmax_k<<<B_*HEADS_*SEQ, 256>>>();
        attn_av_k<<<gAV, 256>>>(v2, DIM_, o);
        sgemm_k<<<gProj, 256>>>(o, wo2_l, b_o2 + l*DIM_, x, x,
                                ROWS, DIM_, DIM_, 0);

        // --- FFN ---
        layernorm_k<<<ROWS, 256>>>(x, ln3_g + l*DIM_, ln3_b + l*DIM_, h);
        sgemm_k<<<gFF1, 256>>>(h, wff1_l, b_ff1 + l*MLP_, nullptr, mlp,
                               ROWS, MLP_, DIM_, 1);
        sgemm_k<<<gProj, 256>>>(mlp, wff2_l, b_ff2 + l*DIM_, x, x,
                                ROWS, DIM_, MLP_, 0);
    }
}

// round 4
// speedup vs baseline: 2.3209x; 2.3209x over previous
#include <cuda_runtime.h>
#include <math.h>
#include <stdint.h>

#define B_      2
#define SEQ     1024
#define DIM_    1024
#define HEADS_  16
#define DH_     64
#define MLP_    4096
#define ROWS    (B_*SEQ)          // 2048
#define SCALE_  0.125f            // 64^-0.5
#define DEPTH_  2

// ---------------- scratch (device globals: allocation-guard-safe) -------------
__device__ float g_h   [ROWS*DIM_];        // 8 MB
__device__ float g_qkv [ROWS*3*DIM_];      // 24 MB
__device__ float g_q2  [ROWS*DIM_];
__device__ float g_k2  [ROWS*DIM_];
__device__ float g_v2  [ROWS*DIM_];
__device__ float g_o   [ROWS*DIM_];
__device__ float g_mlp [ROWS*MLP_];        // 32 MB
__device__ float g_s   [B_*HEADS_*SEQ*SEQ];// 128 MB scores

// ---------------- helpers ------------------------------------------------------
__device__ __forceinline__ uint32_t f2tf(float f) {
    uint32_t r;
    asm("cvt.rna.tf32.f32 %0, %1;" : "=r"(r) : "f"(f));
    return r;
}

__device__ __forceinline__ void mma8(float* c, const uint32_t* a, const uint32_t* b) {
    asm volatile(
        "mma.sync.aligned.m16n8k8.row.col.f32.tf32.tf32.f32 "
        "{%0,%1,%2,%3}, {%4,%5,%6,%7}, {%8,%9}, {%0,%1,%2,%3};"
        : "+f"(c[0]), "+f"(c[1]), "+f"(c[2]), "+f"(c[3])
        : "r"(a[0]), "r"(a[1]), "r"(a[2]), "r"(a[3]),
          "r"(b[0]), "r"(b[1]));
}

// ---------------- layernorm: one block per row ------------------------------
__global__ __launch_bounds__(256) void layernorm_k(
    const float* __restrict__ x, const float* __restrict__ g,
    const float* __restrict__ b, float* __restrict__ out)
{
    __shared__ float red[18];
    const int row = blockIdx.x;
    const int t   = threadIdx.x;
    const float4 v = ((const float4*)(x + (size_t)row*DIM_))[t];
    float s  = v.x + v.y + v.z + v.w;
    float sq = v.x*v.x + v.y*v.y + v.z*v.z + v.w*v.w;
    #pragma unroll
    for (int o = 16; o > 0; o >>= 1) {
        s  += __shfl_down_sync(0xffffffffu, s,  o);
        sq += __shfl_down_sync(0xffffffffu, sq, o);
    }
    if ((t & 31) == 0) { red[t >> 5] = s; red[8 + (t >> 5)] = sq; }
    __syncthreads();
    if (t < 32) {
        float a = (t < 8) ? red[t]     : 0.f;
        float c = (t < 8) ? red[8 + t] : 0.f;
        #pragma unroll
        for (int o = 4; o > 0; o >>= 1) {
            a += __shfl_down_sync(0xffffffffu, a, o);
            c += __shfl_down_sync(0xffffffffu, c, o);
        }
        if (t == 0) { red[16] = a; red[17] = c; }
    }
    __syncthreads();
    const float mu   = red[16] * (1.f / DIM_);
    const float var  = red[17] * (1.f / DIM_) - mu * mu;
    const float rstd = rsqrtf(var + 1e-5f);
    const float4 gv = ((const float4*)g)[t];
    const float4 bv = ((const float4*)b)[t];
    float4 o4;
    o4.x = (v.x - mu) * rstd * gv.x + bv.x;
    o4.y = (v.y - mu) * rstd * gv.y + bv.y;
    o4.z = (v.z - mu) * rstd * gv.z + bv.z;
    o4.w = (v.w - mu) * rstd * gv.w + bv.w;
    ((float4*)(out + (size_t)row*DIM_))[t] = o4;
}

// ---------------- TF32 tensor-core GEMM 128x128x32, 256 thr -------------------
// C[M,N] = act(A[M,K] @ B[K,N] + bias) + res.   M%128==0, N%128==0, K%32==0.
// act: 0 = none, 1 = exact GELU.
//
// SMEM layouts hold operands in mma.m16n8k8 fragment order:
//   A word addr: ((reg*4 + j)*8 + i)*33 + lane      (reg 0..3, j=k8 idx, i=m16 idx)
//   B word addr: ((j*2 + reg)*16 + nt)*33 + lane    (reg 0..1, nt=n8 idx)
// Compute-side LDS is conflict-free (bank == lane); fill-side STS <= 2-way.
__global__ __launch_bounds__(256) void tcgemm_k(
    const float* __restrict__ A, const float* __restrict__ B,
    const float* __restrict__ bias, const float* __restrict__ res,
    float* __restrict__ C, int M, int N, int K, int act)
{
    __shared__ uint32_t As[4224];   // 4*4*8*33
    __shared__ uint32_t Bs[4224];   // 4*2*16*33

    const int tid    = threadIdx.x;
    const int lane   = tid & 31;
    const int warp   = tid >> 5;
    const int warp_m = warp >> 2;        // 0..1
    const int warp_n = warp & 3;         // 0..3
    const int bm = blockIdx.y, bn = blockIdx.x;

    // global-load assignments (fully coalesced)
    const int ar  = tid >> 3;            // A row base 0..31 (+32*it)
    const int aq  = tid & 7;             // A float4-col 0..7
    const int bkr = tid >> 5;            // B k-row base 0..7 (+8*it)
    const int bq  = tid & 31;            // B float4-col 0..31

    const float* Abase = A + (size_t)(bm*128)*K;
    const float* Bbase = B + (size_t)(bn*128);

    // precomputed store indices
    const int a_j    = aq >> 1;
    const int a_reg0 = (aq & 1) * 2;
    const int b_nt   = bq >> 1;
    const int b_lb   = 16*(bq & 1);

    float4 pa[4], pb[4];
    #pragma unroll
    for (int it = 0; it < 4; it++) {
        pa[it] = *(const float4*)(Abase + (size_t)(ar + it*32)*K + aq*4);
        pb[it] = *(const float4*)(Bbase + (size_t)(bkr + it*8)*N + bq*4);
    }

    float acc[4][4][4];
    #pragma unroll
    for (int mi = 0; mi < 4; mi++)
        #pragma unroll
        for (int ni = 0; ni < 4; ni++)
            #pragma unroll
            for (int r = 0; r < 4; r++) acc[mi][ni][r] = 0.f;

    for (int kt = 0; kt < K; kt += 32) {
        // ---- store prefetched tile into fragment-ordered SMEM ----
        #pragma unroll
        for (int it = 0; it < 4; it++) {
            {   // A element (row, k = kt + aq*4 + e)
                const int row  = ar + it*32;
                const int reg  = a_reg0 + (((row & 15) >= 8) ? 1 : 0);
                const int i    = row >> 4;
                const int l0   = 4*(row & 7);
                uint32_t* d = &As[((reg*4 + a_j)*8 + i)*33 + l0];
                d[0] = f2tf(pa[it].x); d[1] = f2tf(pa[it].y);
                d[2] = f2tf(pa[it].z); d[3] = f2tf(pa[it].w);
            }
            {   // B element (k = kt + kb, n = bq*4 + e)
                const int kb  = bkr + it*8;
                const int j   = kb >> 3;
                const int reg = ((kb & 7) >= 4) ? 1 : 0;
                uint32_t* d = &Bs[((j*2 + reg)*16 + b_nt)*33 + b_lb + (kb & 3)];
                d[0]  = f2tf(pb[it].x); d[4]  = f2tf(pb[it].y);
                d[8]  = f2tf(pb[it].z); d[12] = f2tf(pb[it].w);
            }
        }
        __syncthreads();

        // ---- prefetch next k-tile (overlaps with MMA work below) ----
        if (kt + 32 < K) {
            #pragma unroll
            for (int it = 0; it < 4; it++) {
                pa[it] = *(const float4*)(Abase + (size_t)(ar + it*32)*K + (kt + 32) + aq*4);
                pb[it] = *(const float4*)(Bbase + (size_t)(bkr + it*8 + kt + 32)*N + bq*4);
            }
        }

        // ---- MMA over the 4 k8 slices ----
        #pragma unroll
        for (int j = 0; j < 4; j++) {
            uint32_t af[4][4];
            #pragma unroll
            for (int mi = 0; mi < 4; mi++) {
                const int i = warp_m*4 + mi;
                #pragma unroll
                for (int r = 0; r < 4; r++)
                    af[mi][r] = As[((r*4 + j)*8 + i)*33 + lane];
            }
            uint32_t bf[4][2];
            #pragma unroll
            for (int ni = 0; ni < 4; ni++) {
                const int nt = warp_n*4 + ni;
                #pragma unroll
                for (int r = 0; r < 2; r++)
                    bf[ni][r] = Bs[((j*2 + r)*16 + nt)*33 + lane];
            }
            #pragma unroll
            for (int mi = 0; mi < 4; mi++)
                #pragma unroll
                for (int ni = 0; ni < 4; ni++)
                    mma8(acc[mi][ni], af[mi], bf[ni]);
        }
        __syncthreads();
    }

    // ---- epilogue ----
    const int r0 = bm*128 + warp_m*64 + (lane >> 2);
    const int c0 = bn*128 + warp_n*32 + 2*(lane & 3);
    #pragma unroll
    for (int mi = 0; mi < 4; mi++) {
        #pragma unroll
        for (int ni = 0; ni < 4; ni++) {
            const int c = c0 + ni*8;
            float2 bv = make_float2(0.f, 0.f);
            if (bias) bv = *(const float2*)&bias[c];
            #pragma unroll
            for (int half = 0; half < 2; half++) {
                const int r = r0 + mi*16 + half*8;
                const size_t idx = (size_t)r * N + c;
                float vx = acc[mi][ni][half*2 + 0] + bv.x;
                float vy = acc[mi][ni][half*2 + 1] + bv.y;
                if (act == 1) { vx = vx * normcdff(vx); vy = vy * normcdff(vy); }
                if (res) { vx += res[idx]; vy += res[idx + 1]; }
                *(float2*)&C[idx] = make_float2(vx, vy);
            }
        }
    }
}

// ---------------- attention: S = scale * Q K^T (per batch-head) --------------
__global__ __launch_bounds__(256) void attn_qk_k(
    const float* __restrict__ Q, int ldq,
    const float* __restrict__ Kp, int ldk,
    float* __restrict__ S)
{
    const int bh = blockIdx.z, b = bh >> 4, h = bh & 15;
    const int qt = blockIdx.y * 64, kt = blockIdx.x * 64;
    const float* qb = Q  + (size_t)(b*SEQ + qt) * ldq + h*DH_;
    const float* kb = Kp + (size_t)(b*SEQ + kt) * ldk + h*DH_;
    float* sb = g_s + (size_t)bh * SEQ * SEQ;
    (void)S;

    __shared__ float Qs[64][65];
    __shared__ float Ks[64][65];
    const int tid = threadIdx.x;
    for (int i = tid; i < 64*16; i += 256) {
        const int r = i >> 4, c4 = (i & 15) * 4;
        const float4 v = *(const float4*)(qb + (size_t)r*ldq + c4);
        Qs[c4+0][r]=v.x; Qs[c4+1][r]=v.y; Qs[c4+2][r]=v.z; Qs[c4+3][r]=v.w;
        const float4 w = *(const float4*)(kb + (size_t)r*ldk + c4);
        Ks[c4+0][r]=w.x; Ks[c4+1][r]=w.y; Ks[c4+2][r]=w.z; Ks[c4+3][r]=w.w;
    }
    __syncthreads();

    const int tx = tid & 15, ty = tid >> 4;
    float acc[4][4];
    #pragma unroll
    for (int i = 0; i < 4; i++)
        #pragma unroll
        for (int j = 0; j < 4; j++) acc[i][j] = 0.f;

    #pragma unroll 4
    for (int k = 0; k < 64; k++) {
        float ar[4], br[4];
        #pragma unroll
        for (int i = 0; i < 4; i++) ar[i] = Qs[k][ty*4 + i];
        #pragma unroll
        for (int j = 0; j < 4; j++) br[j] = Ks[k][tx*4 + j];
        #pragma unroll
        for (int i = 0; i < 4; i++)
            #pragma unroll
            for (int j = 0; j < 4; j++)
                acc[i][j] = fmaf(ar[i], br[j], acc[i][j]);
    }
    #pragma unroll
    for (int i = 0; i < 4; i++)
        #pragma unroll
        for (int j = 0; j < 4; j++)
            sb[(size_t)(qt + ty*4 + i) * SEQ + kt + tx*4 + j] = acc[i][j] * SCALE_;
}

// ---------------- row softmax over S (SEQ cols) -------------------------------
__global__ __launch_bounds__(256) void softmax_k()
{
    __shared__ float red[16];
    float* p = g_s + (size_t)blockIdx.x * SEQ;
    const int t = threadIdx.x;
    float4 v = ((float4*)p)[t];
    float m = fmaxf(fmaxf(v.x, v.y), fmaxf(v.z, v.w));
    #pragma unroll
    for (int o = 16; o > 0; o >>= 1) m = fmaxf(m, __shfl_xor_sync(0xffffffffu, m, o));
    if ((t & 31) == 0) red[t >> 5] = m;
    __syncthreads();
    m = red[0];
    #pragma unroll
    for (int i = 1; i < 8; i++) m = fmaxf(m, red[i]);

    v.x = __expf(v.x - m); v.y = __expf(v.y - m);
    v.z = __expf(v.z - m); v.w = __expf(v.w - m);
    float s = v.x + v.y + v.z + v.w;
    #pragma unroll
    for (int o = 16; o > 0; o >>= 1) s += __shfl_xor_sync(0xffffffffu, s, o);
    if ((t & 31) == 0) red[8 + (t >> 5)] = s;
    __syncthreads();
    s = red[8];
    #pragma unroll
    for (int i = 1; i < 8; i++) s += red[8 + i];
    const float inv = 1.f / s;
    v.x *= inv; v.y *= inv; v.z *= inv; v.w *= inv;
    ((float4*)p)[t] = v;
}

// ---------------- O = P @ V, writes merged-head layout ------------------------
__global__ __launch_bounds__(256) void attn_av_k(
    const float* __restrict__ V, int ldv, float* __restrict__ O)
{
    const int bh = blockIdx.y, b = bh >> 4, h = bh & 15;
    const int nt = blockIdx.x * 64;
    const float* sb = g_s + (size_t)bh * SEQ * SEQ + (size_t)nt * SEQ;
    const float* vb = V + (size_t)(b*SEQ) * ldv + h*DH_;
    float* ob = O + (size_t)(b*SEQ + nt) * DIM_ + h*DH_;

    __shared__ float Ps[64][65];
    __shared__ float Vs[64][65];
    const int tid = threadIdx.x;
    const int tx = tid & 15, ty = tid >> 4;
    float acc[4][4];
    #pragma unroll
    for (int i = 0; i < 4; i++)
        #pragma unroll
        for (int j = 0; j < 4; j++) acc[i][j] = 0.f;

    for (int mt = 0; mt < SEQ; mt += 64) {
        for (int i = tid; i < 64*16; i += 256) {
            const int r = i >> 4, c4 = (i & 15) * 4;
            const float4 v = *(const float4*)(sb + (size_t)r*SEQ + mt + c4);
            Ps[c4+0][r]=v.x; Ps[c4+1][r]=v.y; Ps[c4+2][r]=v.z; Ps[c4+3][r]=v.w;
            const float4 w = *(const float4*)(vb + (size_t)(mt + r)*ldv + c4);
            Vs[r][c4+0]=w.x; Vs[r][c4+1]=w.y; Vs[r][c4+2]=w.z; Vs[r][c4+3]=w.w;
        }
        __syncthreads();
        #pragma unroll 4
        for (int m = 0; m < 64; m++) {
            float pr[4], vr[4];
            #pragma unroll
            for (int i = 0; i < 4; i++) pr[i] = Ps[m][ty*4 + i];
            #pragma unroll
            for (int j = 0; j < 4; j++) vr[j] = Vs[m][tx*4 + j];
            #pragma unroll
            for (int i = 0; i < 4; i++)
                #pragma unroll
                for (int j = 0; j < 4; j++)
                    acc[i][j] = fmaf(pr[i], vr[j], acc[i][j]);
        }
        __syncthreads();
    }
    #pragma unroll
    for (int i = 0; i < 4; i++)
        #pragma unroll
        for (int j = 0; j < 4; j++)
            ob[(size_t)(ty*4 + i) * DIM_ + tx*4 + j] = acc[i][j];
}

// ---------------- host launch --------------------------------------------------
extern "C" void kernel_launch(void* const* d_in, const int* in_sizes, int n_in,
                              void* d_out, int out_size)
{
    (void)in_sizes; (void)n_in; (void)out_size;
    const float* x_in  = (const float*)d_in[0];
    const float* ctx   = (const float*)d_in[1];
    const float* ln1_g = (const float*)d_in[2];
    const float* ln1_b = (const float*)d_in[3];
    const float* w_qkv = (const float*)d_in[4];
    const float* w_o1  = (const float*)d_in[5];
    const float* b_o1  = (const float*)d_in[6];
    const float* ln2_g = (const float*)d_in[7];
    const float* ln2_b = (const float*)d_in[8];
    const float* w_q   = (const float*)d_in[9];
    const float* w_k   = (const float*)d_in[10];
    const float* w_v   = (const float*)d_in[11];
    const float* w_o2  = (const float*)d_in[12];
    const float* b_o2  = (const float*)d_in[13];
    const float* ln3_g = (const float*)d_in[14];
    const float* ln3_b = (const float*)d_in[15];
    const float* w_ff1 = (const float*)d_in[16];
    const float* b_ff1 = (const float*)d_in[17];
    const float* w_ff2 = (const float*)d_in[18];
    const float* b_ff2 = (const float*)d_in[19];

    float* x = (float*)d_out;

    float *h, *qkv, *q2, *k2, *v2, *o, *mlp, *s;
    cudaGetSymbolAddress((void**)&h,   g_h);
    cudaGetSymbolAddress((void**)&qkv, g_qkv);
    cudaGetSymbolAddress((void**)&q2,  g_q2);
    cudaGetSymbolAddress((void**)&k2,  g_k2);
    cudaGetSymbolAddress((void**)&v2,  g_v2);
    cudaGetSymbolAddress((void**)&o,   g_o);
    cudaGetSymbolAddress((void**)&mlp, g_mlp);
    cudaGetSymbolAddress((void**)&s,   g_s);

    cudaMemcpyAsync(x, x_in, (size_t)ROWS * DIM_ * sizeof(float),
                    cudaMemcpyDeviceToDevice, 0);

    const dim3 gProj(DIM_/128,  ROWS/128);     // (8,16)
    const dim3 gQKV(3*DIM_/128, ROWS/128);     // (24,16)
    const dim3 gFF1(MLP_/128,   ROWS/128);     // (32,16)
    const dim3 gQK(16, 16, B_*HEADS_);
    const dim3 gAV(16, B_*HEADS_);

    for (int l = 0; l < DEPTH_; l++) {
        const float* wqkv_l = w_qkv + (size_t)l * DIM_ * 3*DIM_;
        const float* wo1_l  = w_o1  + (size_t)l * DIM_ * DIM_;
        const float* wq_l   = w_q   + (size_t)l * DIM_ * DIM_;
        const float* wk_l   = w_k   + (size_t)l * DIM_ * DIM_;
        const float* wv_l   = w_v   + (size_t)l * DIM_ * DIM_;
        const float* wo2_l  = w_o2  + (size_t)l * DIM_ * DIM_;
        const float* wff1_l = w_ff1 + (size_t)l * DIM_ * MLP_;
        const float* wff2_l = w_ff2 + (size_t)l * MLP_ * DIM_;

        // --- self attention ---
        layernorm_k<<<ROWS, 256>>>(x, ln1_g + l*DIM_, ln1_b + l*DIM_, h);
        tcgemm_k<<<gQKV, 256>>>(h, wqkv_l, nullptr, nullptr, qkv,
                                ROWS, 3*DIM_, DIM_, 0);
        attn_qk_k<<<gQK, 256>>>(qkv, 3*DIM_, qkv + DIM_, 3*DIM_, s);
        softmax_k<<<B_*HEADS_*SEQ, 256>>>();
        attn_av_k<<<gAV, 256>>>(qkv + 2*DIM_, 3*DIM_, o);
        tcgemm_k<<<gProj, 256>>>(o, wo1_l, b_o1 + l*DIM_, x, x,
                                 ROWS, DIM_, DIM_, 0);

        // --- cross attention ---
        layernorm_k<<<ROWS, 256>>>(x, ln2_g + l*DIM_, ln2_b + l*DIM_, h);
        tcgemm_k<<<gProj, 256>>>(h,   wq_l, nullptr, nullptr, q2, ROWS, DIM_, DIM_, 0);
        tcgemm_k<<<gProj, 256>>>(ctx, wk_l, nullptr, nullptr, k2, ROWS, DIM_, DIM_, 0);
        tcgemm_k<<<gProj, 256>>>(ctx, wv_l, nullptr, nullptr, v2, ROWS, DIM_, DIM_, 0);
        attn_qk_k<<<gQK, 256>>>(q2, DIM_, k2, DIM_, s);
        softmax_k<<<B_*HEADS_*SEQ, 256>>>();
        attn_av_k<<<gAV, 256>>>(v2, DIM_, o);
        tcgemm_k<<<gProj, 256>>>(o, wo2_l, b_o2 + l*DIM_, x, x,
                                 ROWS, DIM_, DIM_, 0);

        // --- FFN ---
        layernorm_k<<<ROWS, 256>>>(x, ln3_g + l*DIM_, ln3_b + l*DIM_, h);
        tcgemm_k<<<gFF1, 256>>>(h, wff1_l, b_ff1 + l*MLP_, nullptr, mlp,
                                ROWS, MLP_, DIM_, 1);
        tcgemm_k<<<gProj, 256>>>(mlp, wff2_l, b_ff2 + l*DIM_, x, x,
                                 ROWS, DIM_, MLP_, 0);
    }
}

// round 5
// speedup vs baseline: 3.7020x; 1.5951x over previous
#include <cuda_runtime.h>
#include <math.h>
#include <stdint.h>

#define B_      2
#define SEQ     1024
#define DIM_    1024
#define HEADS_  16
#define DH_     64
#define MLP_    4096
#define ROWS    (B_*SEQ)          // 2048
#define SCALE_  0.125f            // 64^-0.5
#define DEPTH_  2

// ---------------- scratch (device globals: allocation-guard-safe) -------------
__device__ float g_h   [ROWS*DIM_];
__device__ float g_qkv [ROWS*3*DIM_];
__device__ float g_q2  [ROWS*DIM_];
__device__ float g_k2  [ROWS*DIM_];
__device__ float g_v2  [ROWS*DIM_];
__device__ float g_o   [ROWS*DIM_];
__device__ float g_mlp [ROWS*MLP_];

// ---------------- helpers ------------------------------------------------------
__device__ __forceinline__ uint32_t f2tf(float f) {
    uint32_t r;
    asm("cvt.rna.tf32.f32 %0, %1;" : "=r"(r) : "f"(f));
    return r;
}

__device__ __forceinline__ void mma8(float* c, const uint32_t* a, const uint32_t* b) {
    asm volatile(
        "mma.sync.aligned.m16n8k8.row.col.f32.tf32.tf32.f32 "
        "{%0,%1,%2,%3}, {%4,%5,%6,%7}, {%8,%9}, {%0,%1,%2,%3};"
        : "+f"(c[0]), "+f"(c[1]), "+f"(c[2]), "+f"(c[3])
        : "r"(a[0]), "r"(a[1]), "r"(a[2]), "r"(a[3]),
          "r"(b[0]), "r"(b[1]));
}

// A-fragment word index for M=64,K=64 tile (m16n8k8):
//   reg encodes (k bit2, row bit3); j = k>>3; i = row>>4; lane = (row&7)*4 + (k&3)
__device__ __forceinline__ int aidx(int row, int k) {
    const int reg = ((k & 7) >> 2) * 2 + ((row & 15) >> 3);
    return (((reg * 8 + (k >> 3)) * 4 + (row >> 4)) * 33) + (row & 7) * 4 + (k & 3);
}
// B-fragment word index for N=64,K=64 tile:
__device__ __forceinline__ int bidx(int n, int k) {
    const int reg = (k & 4) >> 2;
    return ((((k >> 3) * 2 + reg) * 8 + (n >> 3)) * 33) + (n & 7) * 4 + (k & 3);
}

// ---------------- layernorm: one block per row ------------------------------
__global__ __launch_bounds__(256) void layernorm_k(
    const float* __restrict__ x, const float* __restrict__ g,
    const float* __restrict__ b, float* __restrict__ out)
{
    __shared__ float red[18];
    const int row = blockIdx.x;
    const int t   = threadIdx.x;
    const float4 v = ((const float4*)(x + (size_t)row*DIM_))[t];
    float s  = v.x + v.y + v.z + v.w;
    float sq = v.x*v.x + v.y*v.y + v.z*v.z + v.w*v.w;
    #pragma unroll
    for (int o = 16; o > 0; o >>= 1) {
        s  += __shfl_down_sync(0xffffffffu, s,  o);
        sq += __shfl_down_sync(0xffffffffu, sq, o);
    }
    if ((t & 31) == 0) { red[t >> 5] = s; red[8 + (t >> 5)] = sq; }
    __syncthreads();
    if (t < 32) {
        float a = (t < 8) ? red[t]     : 0.f;
        float c = (t < 8) ? red[8 + t] : 0.f;
        #pragma unroll
        for (int o = 4; o > 0; o >>= 1) {
            a += __shfl_down_sync(0xffffffffu, a, o);
            c += __shfl_down_sync(0xffffffffu, c, o);
        }
        if (t == 0) { red[16] = a; red[17] = c; }
    }
    __syncthreads();
    const float mu   = red[16] * (1.f / DIM_);
    const float var  = red[17] * (1.f / DIM_) - mu * mu;
    const float rstd = rsqrtf(var + 1e-5f);
    const float4 gv = ((const float4*)g)[t];
    const float4 bv = ((const float4*)b)[t];
    float4 o4;
    o4.x = (v.x - mu) * rstd * gv.x + bv.x;
    o4.y = (v.y - mu) * rstd * gv.y + bv.y;
    o4.z = (v.z - mu) * rstd * gv.z + bv.z;
    o4.w = (v.w - mu) * rstd * gv.w + bv.w;
    ((float4*)(out + (size_t)row*DIM_))[t] = o4;
}

// ---------------- TF32 tensor-core GEMM 128x128x32, 256 thr -------------------
__global__ __launch_bounds__(256) void tcgemm_k(
    const float* __restrict__ A, const float* __restrict__ B,
    const float* __restrict__ bias, const float* __restrict__ res,
    float* __restrict__ C, int M, int N, int K, int act)
{
    __shared__ uint32_t As[4224];
    __shared__ uint32_t Bs[4224];

    const int tid    = threadIdx.x;
    const int lane   = tid & 31;
    const int warp   = tid >> 5;
    const int warp_m = warp >> 2;
    const int warp_n = warp & 3;
    const int bm = blockIdx.y, bn = blockIdx.x;

    const int ar  = tid >> 3;
    const int aq  = tid & 7;
    const int bkr = tid >> 5;
    const int bq  = tid & 31;

    const float* Abase = A + (size_t)(bm*128)*K;
    const float* Bbase = B + (size_t)(bn*128);

    const int a_j    = aq >> 1;
    const int a_reg0 = (aq & 1) * 2;
    const int b_nt   = bq >> 1;
    const int b_lb   = 16*(bq & 1);

    float4 pa[4], pb[4];
    #pragma unroll
    for (int it = 0; it < 4; it++) {
        pa[it] = *(const float4*)(Abase + (size_t)(ar + it*32)*K + aq*4);
        pb[it] = *(const float4*)(Bbase + (size_t)(bkr + it*8)*N + bq*4);
    }

    float acc[4][4][4];
    #pragma unroll
    for (int mi = 0; mi < 4; mi++)
        #pragma unroll
        for (int ni = 0; ni < 4; ni++)
            #pragma unroll
            for (int r = 0; r < 4; r++) acc[mi][ni][r] = 0.f;

    for (int kt = 0; kt < K; kt += 32) {
        #pragma unroll
        for (int it = 0; it < 4; it++) {
            {
                const int row  = ar + it*32;
                const int reg  = a_reg0 + (((row & 15) >= 8) ? 1 : 0);
                const int i    = row >> 4;
                const int l0   = 4*(row & 7);
                uint32_t* d = &As[((reg*4 + a_j)*8 + i)*33 + l0];
                d[0] = f2tf(pa[it].x); d[1] = f2tf(pa[it].y);
                d[2] = f2tf(pa[it].z); d[3] = f2tf(pa[it].w);
            }
            {
                const int kb  = bkr + it*8;
                const int j   = kb >> 3;
                const int reg = ((kb & 7) >= 4) ? 1 : 0;
                uint32_t* d = &Bs[((j*2 + reg)*16 + b_nt)*33 + b_lb + (kb & 3)];
                d[0]  = f2tf(pb[it].x); d[4]  = f2tf(pb[it].y);
                d[8]  = f2tf(pb[it].z); d[12] = f2tf(pb[it].w);
            }
        }
        __syncthreads();

        if (kt + 32 < K) {
            #pragma unroll
            for (int it = 0; it < 4; it++) {
                pa[it] = *(const float4*)(Abase + (size_t)(ar + it*32)*K + (kt + 32) + aq*4);
                pb[it] = *(const float4*)(Bbase + (size_t)(bkr + it*8 + kt + 32)*N + bq*4);
            }
        }

        #pragma unroll
        for (int j = 0; j < 4; j++) {
            uint32_t af[4][4];
            #pragma unroll
            for (int mi = 0; mi < 4; mi++) {
                const int i = warp_m*4 + mi;
                #pragma unroll
                for (int r = 0; r < 4; r++)
                    af[mi][r] = As[((r*4 + j)*8 + i)*33 + lane];
            }
            uint32_t bf[4][2];
            #pragma unroll
            for (int ni = 0; ni < 4; ni++) {
                const int nt = warp_n*4 + ni;
                #pragma unroll
                for (int r = 0; r < 2; r++)
                    bf[ni][r] = Bs[((j*2 + r)*16 + nt)*33 + lane];
            }
            #pragma unroll
            for (int mi = 0; mi < 4; mi++)
                #pragma unroll
                for (int ni = 0; ni < 4; ni++)
                    mma8(acc[mi][ni], af[mi], bf[ni]);
        }
        __syncthreads();
    }

    const int r0 = bm*128 + warp_m*64 + (lane >> 2);
    const int c0 = bn*128 + warp_n*32 + 2*(lane & 3);
    #pragma unroll
    for (int mi = 0; mi < 4; mi++) {
        #pragma unroll
        for (int ni = 0; ni < 4; ni++) {
            const int c = c0 + ni*8;
            float2 bv = make_float2(0.f, 0.f);
            if (bias) bv = *(const float2*)&bias[c];
            #pragma unroll
            for (int half = 0; half < 2; half++) {
                const int r = r0 + mi*16 + half*8;
                const size_t idx = (size_t)r * N + c;
                float vx = acc[mi][ni][half*2 + 0] + bv.x;
                float vy = acc[mi][ni][half*2 + 1] + bv.y;
                if (act == 1) { vx = vx * normcdff(vx); vy = vy * normcdff(vy); }
                if (res) { vx += res[idx]; vy += res[idx + 1]; }
                *(float2*)&C[idx] = make_float2(vx, vy);
            }
        }
    }
}

// ---------------- fused flash attention (TF32 MMA, online softmax) -----------
// One CTA per (bh, 64-row Q tile). 8 warps: wm = warp>>1 (m16 group),
// wn = warp&1 (column half: 32 cols of S, 32 dh cols of O).
// SMEM (dynamic): Qs[4224] | Ks[4224] (aliased by Ps after S is computed) | Vs[4224]
__global__ __launch_bounds__(256) void flash_k(
    const float* __restrict__ Q, int ldq,
    const float* __restrict__ Kp, int ldk,
    const float* __restrict__ V, int ldv,
    float* __restrict__ O)
{
    extern __shared__ uint32_t fsm[];
    uint32_t* Qs = fsm;
    uint32_t* Ks = fsm + 4224;      // also Ps
    uint32_t* Vs = fsm + 8448;
    __shared__ float row_m[64], row_l[64];
    __shared__ float pmax[2][64], psum[2][64];

    const int bh = blockIdx.y, b = bh >> 4, h = bh & 15;
    const int q0 = blockIdx.x * 64;
    const int tid = threadIdx.x, lane = tid & 31, warp = tid >> 5;
    const int wm = warp >> 1, wn = warp & 1;

    // ---- load Q tile (pre-scaled) into A-frag order ----
    {
        const float* qb = Q + (size_t)(b*SEQ + q0) * ldq + h*DH_;
        const int r  = tid >> 4;         // 0..15 (+16 per it)
        const int c4 = (tid & 15) * 4;
        #pragma unroll
        for (int it = 0; it < 4; it++) {
            const int row = r + it*16;
            const float4 v = *(const float4*)(qb + (size_t)row*ldq + c4);
            uint32_t* d = &Qs[aidx(row, c4)];   // 4 consecutive words
            d[0] = f2tf(v.x * SCALE_); d[1] = f2tf(v.y * SCALE_);
            d[2] = f2tf(v.z * SCALE_); d[3] = f2tf(v.w * SCALE_);
        }
    }
    if (tid < 64) { row_m[tid] = -1e30f; row_l[tid] = 0.f; }

    float o[4][4];
    #pragma unroll
    for (int ni = 0; ni < 4; ni++)
        #pragma unroll
        for (int c = 0; c < 4; c++) o[ni][c] = 0.f;

    const int r0 = wm*16 + (lane >> 2);
    const int r1 = r0 + 8;

    for (int kt = 0; kt < SEQ; kt += 64) {
        __syncthreads();   // protect Ks(=Ps)/Vs from previous iteration's readers

        // ---- load K tile (B-frag, n=kv,k=dh) and V tile (B-frag, n=dh,k=kv) ----
        {
            const float* kb = Kp + (size_t)(b*SEQ + kt) * ldk + h*DH_;
            const float* vb = V  + (size_t)(b*SEQ + kt) * ldv + h*DH_;
            const int r  = tid >> 4;
            const int c4 = (tid & 15) * 4;
            #pragma unroll
            for (int it = 0; it < 4; it++) {
                const int row = r + it*16;
                const float4 kv4 = *(const float4*)(kb + (size_t)row*ldk + c4);
                uint32_t* d = &Ks[bidx(row, c4)];   // 4 consecutive
                d[0] = f2tf(kv4.x); d[1] = f2tf(kv4.y);
                d[2] = f2tf(kv4.z); d[3] = f2tf(kv4.w);
                const float4 vv4 = *(const float4*)(vb + (size_t)row*ldv + c4);
                Vs[bidx(c4+0, row)] = f2tf(vv4.x);
                Vs[bidx(c4+1, row)] = f2tf(vv4.y);
                Vs[bidx(c4+2, row)] = f2tf(vv4.z);
                Vs[bidx(c4+3, row)] = f2tf(vv4.w);
            }
        }
        __syncthreads();

        // ---- S = Q K^T (per warp: m16 x n32 x k64) ----
        float s[4][4];
        #pragma unroll
        for (int ni = 0; ni < 4; ni++)
            #pragma unroll
            for (int c = 0; c < 4; c++) s[ni][c] = 0.f;
        #pragma unroll
        for (int j = 0; j < 8; j++) {
            uint32_t af[4];
            #pragma unroll
            for (int r = 0; r < 4; r++)
                af[r] = Qs[((r*8 + j)*4 + wm)*33 + lane];
            #pragma unroll
            for (int ni = 0; ni < 4; ni++) {
                uint32_t bf[2];
                #pragma unroll
                for (int r = 0; r < 2; r++)
                    bf[r] = Ks[((j*2 + r)*8 + wn*4 + ni)*33 + lane];
                mma8(s[ni], af, bf);
            }
        }

        // ---- online softmax ----
        float mx0 = -1e30f, mx1 = -1e30f;
        #pragma unroll
        for (int ni = 0; ni < 4; ni++) {
            mx0 = fmaxf(mx0, fmaxf(s[ni][0], s[ni][1]));
            mx1 = fmaxf(mx1, fmaxf(s[ni][2], s[ni][3]));
        }
        mx0 = fmaxf(mx0, __shfl_xor_sync(0xffffffffu, mx0, 1));
        mx0 = fmaxf(mx0, __shfl_xor_sync(0xffffffffu, mx0, 2));
        mx1 = fmaxf(mx1, __shfl_xor_sync(0xffffffffu, mx1, 1));
        mx1 = fmaxf(mx1, __shfl_xor_sync(0xffffffffu, mx1, 2));
        if ((lane & 3) == 0) { pmax[wn][r0] = mx0; pmax[wn][r1] = mx1; }
        __syncthreads();

        const float mo0 = row_m[r0], mo1 = row_m[r1];
        const float mn0 = fmaxf(mo0, fmaxf(pmax[0][r0], pmax[1][r0]));
        const float mn1 = fmaxf(mo1, fmaxf(pmax[0][r1], pmax[1][r1]));
        const float al0 = __expf(mo0 - mn0);
        const float al1 = __expf(mo1 - mn1);

        float sum0 = 0.f, sum1 = 0.f;
        #pragma unroll
        for (int ni = 0; ni < 4; ni++) {
            const int cb = wn*32 + ni*8 + (lane & 3)*2;
            float p00 = __expf(s[ni][0] - mn0);
            float p01 = __expf(s[ni][1] - mn0);
            float p10 = __expf(s[ni][2] - mn1);
            float p11 = __expf(s[ni][3] - mn1);
            sum0 += p00 + p01;
            sum1 += p10 + p11;
            Ks[aidx(r0, cb    )] = f2tf(p00);   // Ps aliases Ks
            Ks[aidx(r0, cb + 1)] = f2tf(p01);
            Ks[aidx(r1, cb    )] = f2tf(p10);
            Ks[aidx(r1, cb + 1)] = f2tf(p11);
        }
        sum0 += __shfl_xor_sync(0xffffffffu, sum0, 1);
        sum0 += __shfl_xor_sync(0xffffffffu, sum0, 2);
        sum1 += __shfl_xor_sync(0xffffffffu, sum1, 1);
        sum1 += __shfl_xor_sync(0xffffffffu, sum1, 2);
        if ((lane & 3) == 0) { psum[wn][r0] = sum0; psum[wn][r1] = sum1; }

        // rescale running O
        #pragma unroll
        for (int ni = 0; ni < 4; ni++) {
            o[ni][0] *= al0; o[ni][1] *= al0;
            o[ni][2] *= al1; o[ni][3] *= al1;
        }
        __syncthreads();

        if (wn == 0 && (lane & 3) == 0) {
            row_m[r0] = mn0; row_m[r1] = mn1;
            row_l[r0] = row_l[r0]*al0 + psum[0][r0] + psum[1][r0];
            row_l[r1] = row_l[r1]*al1 + psum[0][r1] + psum[1][r1];
        }

        // ---- O += P V (per warp: m16 x n32(dh) x k64(kv)) ----
        #pragma unroll
        for (int j = 0; j < 8; j++) {
            uint32_t af[4];
            #pragma unroll
            for (int r = 0; r < 4; r++)
                af[r] = Ks[((r*8 + j)*4 + wm)*33 + lane];   // Ps
            #pragma unroll
            for (int ni = 0; ni < 4; ni++) {
                uint32_t bf[2];
                #pragma unroll
                for (int r = 0; r < 2; r++)
                    bf[r] = Vs[((j*2 + r)*8 + wn*4 + ni)*33 + lane];
                mma8(o[ni], af, bf);
            }
        }
    }
    __syncthreads();

    // ---- normalize and write merged-head output ----
    const float inv0 = 1.f / row_l[r0];
    const float inv1 = 1.f / row_l[r1];
    float* ob = O + (size_t)(b*SEQ + q0) * DIM_ + h*DH_;
    #pragma unroll
    for (int ni = 0; ni < 4; ni++) {
        const int c = wn*32 + ni*8 + (lane & 3)*2;
        *(float2*)(ob + (size_t)r0*DIM_ + c) = make_float2(o[ni][0]*inv0, o[ni][1]*inv0);
        *(float2*)(ob + (size_t)r1*DIM_ + c) = make_float2(o[ni][2]*inv1, o[ni][3]*inv1);
    }
}

// ---------------- host launch --------------------------------------------------
extern "C" void kernel_launch(void* const* d_in, const int* in_sizes, int n_in,
                              void* d_out, int out_size)
{
    (void)in_sizes; (void)n_in; (void)out_size;
    const float* x_in  = (const float*)d_in[0];
    const float* ctx   = (const float*)d_in[1];
    const float* ln1_g = (const float*)d_in[2];
    const float* ln1_b = (const float*)d_in[3];
    const float* w_qkv = (const float*)d_in[4];
    const float* w_o1  = (const float*)d_in[5];
    const float* b_o1  = (const float*)d_in[6];
    const float* ln2_g = (const float*)d_in[7];
    const float* ln2_b = (const float*)d_in[8];
    const float* w_q   = (const float*)d_in[9];
    const float* w_k   = (const float*)d_in[10];
    const float* w_v   = (const float*)d_in[11];
    const float* w_o2  = (const float*)d_in[12];
    const float* b_o2  = (const float*)d_in[13];
    const float* ln3_g = (const float*)d_in[14];
    const float* ln3_b = (const float*)d_in[15];
    const float* w_ff1 = (const float*)d_in[16];
    const float* b_ff1 = (const float*)d_in[17];
    const float* w_ff2 = (const float*)d_in[18];
    const float* b_ff2 = (const float*)d_in[19];

    float* x = (float*)d_out;

    float *h, *qkv, *q2, *k2, *v2, *o, *mlp;
    cudaGetSymbolAddress((void**)&h,   g_h);
    cudaGetSymbolAddress((void**)&qkv, g_qkv);
    cudaGetSymbolAddress((void**)&q2,  g_q2);
    cudaGetSymbolAddress((void**)&k2,  g_k2);
    cudaGetSymbolAddress((void**)&v2,  g_v2);
    cudaGetSymbolAddress((void**)&o,   g_o);
    cudaGetSymbolAddress((void**)&mlp, g_mlp);

    const int FLASH_SMEM = 3 * 4224 * 4;   // 50688 B
    cudaFuncSetAttribute(flash_k, cudaFuncAttributeMaxDynamicSharedMemorySize,
                         FLASH_SMEM);

    cudaMemcpyAsync(x, x_in, (size_t)ROWS * DIM_ * sizeof(float),
                    cudaMemcpyDeviceToDevice, 0);

    const dim3 gProj(DIM_/128,  ROWS/128);
    const dim3 gQKV(3*DIM_/128, ROWS/128);
    const dim3 gFF1(MLP_/128,   ROWS/128);
    const dim3 gFl(SEQ/64, B_*HEADS_);

    for (int l = 0; l < DEPTH_; l++) {
        const float* wqkv_l = w_qkv + (size_t)l * DIM_ * 3*DIM_;
        const float* wo1_l  = w_o1  + (size_t)l * DIM_ * DIM_;
        const float* wq_l   = w_q   + (size_t)l * DIM_ * DIM_;
        const float* wk_l   = w_k   + (size_t)l * DIM_ * DIM_;
        const float* wv_l   = w_v   + (size_t)l * DIM_ * DIM_;
        const float* wo2_l  = w_o2  + (size_t)l * DIM_ * DIM_;
        const float* wff1_l = w_ff1 + (size_t)l * DIM_ * MLP_;
        const float* wff2_l = w_ff2 + (size_t)l * MLP_ * DIM_;

        // --- self attention ---
        layernorm_k<<<ROWS, 256>>>(x, ln1_g + l*DIM_, ln1_b + l*DIM_, h);
        tcgemm_k<<<gQKV, 256>>>(h, wqkv_l, nullptr, nullptr, qkv,
                                ROWS, 3*DIM_, DIM_, 0);
        flash_k<<<gFl, 256, FLASH_SMEM>>>(qkv, 3*DIM_, qkv + DIM_, 3*DIM_,
                                          qkv + 2*DIM_, 3*DIM_, o);
        tcgemm_k<<<gProj, 256>>>(o, wo1_l, b_o1 + l*DIM_, x, x,
                                 ROWS, DIM_, DIM_, 0);

        // --- cross attention ---
        layernorm_k<<<ROWS, 256>>>(x, ln2_g + l*DIM_, ln2_b + l*DIM_, h);
        tcgemm_k<<<gProj, 256>>>(h,   wq_l, nullptr, nullptr, q2, ROWS, DIM_, DIM_, 0);
        tcgemm_k<<<gProj, 256>>>(ctx, wk_l, nullptr, nullptr, k2, ROWS, DIM_, DIM_, 0);
        tcgemm_k<<<gProj, 256>>>(ctx, wv_l, nullptr, nullptr, v2, ROWS, DIM_, DIM_, 0);
        flash_k<<<gFl, 256, FLASH_SMEM>>>(q2, DIM_, k2, DIM_, v2, DIM_, o);
        tcgemm_k<<<gProj, 256>>>(o, wo2_l, b_o2 + l*DIM_, x, x,
                                 ROWS, DIM_, DIM_, 0);

        // --- FFN ---
        layernorm_k<<<ROWS, 256>>>(x, ln3_g + l*DIM_, ln3_b + l*DIM_, h);
        tcgemm_k<<<gFF1, 256>>>(h, wff1_l, b_ff1 + l*MLP_, nullptr, mlp,
                                ROWS, MLP_, DIM_, 1);
        tcgemm_k<<<gProj, 256>>>(mlp, wff2_l, b_ff2 + l*DIM_, x, x,
                                 ROWS, DIM_, MLP_, 0);
    }
}